// round 11
// baseline (speedup 1.0000x reference)
#include <cuda_runtime.h>
#include <cuda_fp16.h>
#include <cuda_bf16.h>

#define N_NODES   10000
#define N_EDGES   640000
#define F_IN      128
#define H1        64
#define H2        32
#define N_CLASSES 16

// ---------------- scratch (device globals) ----------------------------------
__device__ uint4 g_h1s [N_NODES * H1 / 8];   // h1 * dinv[n]  (fp16 payload)
__device__ uint4 g_agg1[N_NODES * H1 / 8];   // fp16 accum: init h1s + b1*rd
__device__ uint4 g_h2s [N_NODES * H2 / 8];   // h2 * dinv[n]  (fp16)
__device__ uint4 g_agg2[N_NODES * H2 / 8];   // fp16 accum: init h2s + b2*rd
__device__ int   g_deg [N_NODES];            // ALWAYS zero at launch entry
__device__ float g_colsum[H2];

// 16-byte vectorized fp16 reduction (no return), sm_90+
__device__ __forceinline__ void red_add_v4_f16x2(void* addr, uint4 a) {
    asm volatile("red.global.add.noftz.v4.f16x2 [%0], {%1,%2,%3,%4};"
                 :: "l"(addr), "r"(a.x), "r"(a.y), "r"(a.z), "r"(a.w)
                 : "memory");
}

// ---------------- degree histogram (+ colsum zero) ----------------------------
__global__ void hist_kernel(const int* __restrict__ ei) {
    int e = blockIdx.x * blockDim.x + threadIdx.x;
    if (blockIdx.x == 0 && threadIdx.x < H2) g_colsum[threadIdx.x] = 0.0f;
    if (e >= N_EDGES) return;
    atomicAdd(&g_deg[ei[N_EDGES + e]], 1);   // no-return -> RED
}

// ---------------- gemm1: h1 = x @ W1 -----------------------------------------
// 64 nodes x 64 outs, 256 threads, micro 4x4, two K chunks of 64.
// epilogue (fp16): h1s = h1*d;  agg1 = h1s + b1*rd  (true act = relu(agg1*d))
__global__ __launch_bounds__(256) void gemm1_kernel(const float* __restrict__ x,
                                                    const float* __restrict__ W1,
                                                    const float* __restrict__ b1) {
    __shared__ float Ws[64][64];
    __shared__ float Xt[64][68];

    const int tid = threadIdx.x;
    const int tx  = tid & 15;
    const int ty  = tid >> 4;
    const int node0 = blockIdx.x * 64;

    float acc[4][4];
#pragma unroll
    for (int i = 0; i < 4; i++)
#pragma unroll
        for (int j = 0; j < 4; j++) acc[i][j] = 0.0f;

    for (int kc = 0; kc < 2; kc++) {
        {
            int r  = tid >> 4;
            int c4 = (tid & 15) * 4;
#pragma unroll
            for (int p = 0; p < 4; p++) {
                int rr = r + p * 16;
                *(float4*)(&Ws[rr][c4]) =
                    *(const float4*)(W1 + (kc * 64 + rr) * H1 + c4);
            }
        }
        {
            int nl = tid & 63;
            int kq = (tid >> 6) * 4;
            int node = node0 + nl;
#pragma unroll
            for (int p = 0; p < 4; p++) {
                int k4 = kq + p * 16;
                float4 v = make_float4(0.f, 0.f, 0.f, 0.f);
                if (node < N_NODES)
                    v = *(const float4*)(x + node * F_IN + kc * 64 + k4);
                Xt[k4 + 0][nl] = v.x; Xt[k4 + 1][nl] = v.y;
                Xt[k4 + 2][nl] = v.z; Xt[k4 + 3][nl] = v.w;
            }
        }
        __syncthreads();

#pragma unroll 8
        for (int k = 0; k < 64; k++) {
            float4 wv = *(const float4*)(&Ws[k][tx * 4]);
            float4 xv = *(const float4*)(&Xt[k][ty * 4]);
            acc[0][0] += xv.x * wv.x; acc[0][1] += xv.x * wv.y;
            acc[0][2] += xv.x * wv.z; acc[0][3] += xv.x * wv.w;
            acc[1][0] += xv.y * wv.x; acc[1][1] += xv.y * wv.y;
            acc[1][2] += xv.y * wv.z; acc[1][3] += xv.y * wv.w;
            acc[2][0] += xv.z * wv.x; acc[2][1] += xv.z * wv.y;
            acc[2][2] += xv.z * wv.z; acc[2][3] += xv.z * wv.w;
            acc[3][0] += xv.w * wv.x; acc[3][1] += xv.w * wv.y;
            acc[3][2] += xv.w * wv.z; acc[3][3] += xv.w * wv.w;
        }
        __syncthreads();
    }

    float4 bv = *(const float4*)(b1 + tx * 4);
#pragma unroll
    for (int i = 0; i < 4; i++) {
        int node = node0 + ty * 4 + i;
        if (node < N_NODES) {
            float dp1 = (float)g_deg[node] + 1.0f;
            float d   = rsqrtf(dp1);
            float rd  = dp1 * d;              // sqrt(deg+1)
            float4 hs = make_float4(acc[i][0] * d, acc[i][1] * d,
                                    acc[i][2] * d, acc[i][3] * d);
            __half2 hp0 = __floats2half2_rn(hs.x, hs.y);
            __half2 hp1 = __floats2half2_rn(hs.z, hs.w);
            *(uint2*)((__half*)g_h1s + node * H1 + tx * 4) =
                make_uint2(*(unsigned*)&hp0, *(unsigned*)&hp1);
            __half2 ap0 = __floats2half2_rn(hs.x + bv.x * rd, hs.y + bv.y * rd);
            __half2 ap1 = __floats2half2_rn(hs.z + bv.z * rd, hs.w + bv.w * rd);
            *(uint2*)((__half*)g_agg1 + node * H1 + tx * 4) =
                make_uint2(*(unsigned*)&ap0, *(unsigned*)&ap1);
        }
    }
}

// ---------------- edge aggregation layer 1 -----------------------------------
// 4 threads per edge, 32B fp16 slice each: 2 independent gather+red pairs.
__global__ void agg1_kernel(const int* __restrict__ ei) {
    long long t = (long long)blockIdx.x * blockDim.x + threadIdx.x;
    int e = (int)(t >> 2);
    int q = (int)(t & 3);
    if (e >= N_EDGES) return;
    int src = __ldg(&ei[e]);
    int dst = __ldg(&ei[N_EDGES + e]);
    uint4 a0 = g_h1s[src * 8 + q * 2 + 0];
    uint4 a1 = g_h1s[src * 8 + q * 2 + 1];
    red_add_v4_f16x2(g_agg1 + dst * 8 + q * 2 + 0, a0);
    red_add_v4_f16x2(g_agg1 + dst * 8 + q * 2 + 1, a1);
}

// ---------------- gemm2: h2 = relu(agg1*d) @ W2 ------------------------------
// 64 nodes x 32 outs, 128 threads, micro 4x4; fp16 agg1 -> fp32 smem with
// deferred dinv + relu. epilogue (fp16): h2s = h2*d; agg2 = h2s + b2*rd.
__global__ __launch_bounds__(128) void gemm2_kernel(const float* __restrict__ W2,
                                                    const float* __restrict__ b2) {
    __shared__ float Ws[64][32];
    __shared__ float Xt[64][68];

    const int tid = threadIdx.x;
    const int tx  = tid & 7;
    const int ty  = tid >> 3;
    const int node0 = blockIdx.x * 64;

    {
        int r  = tid >> 3;
        int c4 = (tid & 7) * 4;
#pragma unroll
        for (int p = 0; p < 4; p++) {
            int rr = r + p * 16;
            *(float4*)(&Ws[rr][c4]) = *(const float4*)(W2 + rr * H2 + c4);
        }
    }
    {
        int nl = tid & 63;                 // node local
        int hsel = tid >> 6;               // 0/1 -> k half [0,32) or [32,64)
        int node = node0 + nl;
        float d = 0.f;
        if (node < N_NODES) d = rsqrtf((float)g_deg[node] + 1.0f);
#pragma unroll
        for (int p = 0; p < 4; p++) {
            int k8 = hsel * 32 + p * 8;
            uint4 raw = make_uint4(0, 0, 0, 0);
            if (node < N_NODES)
                raw = g_agg1[node * 8 + hsel * 4 + p];
            __half2* hp = (__half2*)&raw;
#pragma unroll
            for (int u = 0; u < 4; u++) {
                float2 f = __half22float2(hp[u]);
                Xt[k8 + u * 2 + 0][nl] = fmaxf(f.x * d, 0.f);
                Xt[k8 + u * 2 + 1][nl] = fmaxf(f.y * d, 0.f);
            }
        }
    }
    __syncthreads();

    float acc[4][4];
#pragma unroll
    for (int i = 0; i < 4; i++)
#pragma unroll
        for (int j = 0; j < 4; j++) acc[i][j] = 0.0f;

#pragma unroll 8
    for (int k = 0; k < 64; k++) {
        float4 wv = *(const float4*)(&Ws[k][tx * 4]);
        float4 xv = *(const float4*)(&Xt[k][ty * 4]);
        acc[0][0] += xv.x * wv.x; acc[0][1] += xv.x * wv.y;
        acc[0][2] += xv.x * wv.z; acc[0][3] += xv.x * wv.w;
        acc[1][0] += xv.y * wv.x; acc[1][1] += xv.y * wv.y;
        acc[1][2] += xv.y * wv.z; acc[1][3] += xv.y * wv.w;
        acc[2][0] += xv.z * wv.x; acc[2][1] += xv.z * wv.y;
        acc[2][2] += xv.z * wv.z; acc[2][3] += xv.z * wv.w;
        acc[3][0] += xv.w * wv.x; acc[3][1] += xv.w * wv.y;
        acc[3][2] += xv.w * wv.z; acc[3][3] += xv.w * wv.w;
    }

    float4 bv = *(const float4*)(b2 + tx * 4);
#pragma unroll
    for (int i = 0; i < 4; i++) {
        int node = node0 + ty * 4 + i;
        if (node < N_NODES) {
            float dp1 = (float)g_deg[node] + 1.0f;
            float d   = rsqrtf(dp1);
            float rd  = dp1 * d;
            float4 hs = make_float4(acc[i][0] * d, acc[i][1] * d,
                                    acc[i][2] * d, acc[i][3] * d);
            __half2 hp0 = __floats2half2_rn(hs.x, hs.y);
            __half2 hp1 = __floats2half2_rn(hs.z, hs.w);
            *(uint2*)((__half*)g_h2s + node * H2 + tx * 4) =
                make_uint2(*(unsigned*)&hp0, *(unsigned*)&hp1);
            __half2 ap0 = __floats2half2_rn(hs.x + bv.x * rd, hs.y + bv.y * rd);
            __half2 ap1 = __floats2half2_rn(hs.z + bv.z * rd, hs.w + bv.w * rd);
            *(uint2*)((__half*)g_agg2 + node * H2 + tx * 4) =
                make_uint2(*(unsigned*)&ap0, *(unsigned*)&ap1);
        }
    }
}

// ---------------- edge aggregation layer 2 -----------------------------------
// 2 threads per edge, 32B fp16 slice each: 2 independent gather+red pairs.
__global__ void agg2_kernel(const int* __restrict__ ei) {
    long long t = (long long)blockIdx.x * blockDim.x + threadIdx.x;
    int e = (int)(t >> 1);
    int q = (int)(t & 1);
    if (e >= N_EDGES) return;
    int src = __ldg(&ei[e]);
    int dst = __ldg(&ei[N_EDGES + e]);
    uint4 a0 = g_h2s[src * 4 + q * 2 + 0];
    uint4 a1 = g_h2s[src * 4 + q * 2 + 1];
    red_add_v4_f16x2(g_agg2 + dst * 4 + q * 2 + 0, a0);
    red_add_v4_f16x2(g_agg2 + dst * 4 + q * 2 + 1, a1);
}

// ---------------- layer-2 epilogue: relu(agg2*d) + mean-pool column sums -----
// NOTE: reads g_deg but does NOT reset it (reset happens in final_kernel,
// which is stream-ordered after this kernel completes).
__global__ void post2_kernel() {
    __shared__ float s[256];
    int t = blockIdx.x * blockDim.x + threadIdx.x;   // over N_NODES*H2
    float v = 0.0f;
    if (t < N_NODES * H2) {
        int n = t >> 5;
        float d = rsqrtf((float)g_deg[n] + 1.0f);
        float a = __half2float(((const __half*)g_agg2)[t]);
        v = fmaxf(a * d, 0.0f);
    }
    s[threadIdx.x] = v;
    __syncthreads();
#pragma unroll
    for (int st = 128; st >= 32; st >>= 1) {
        if (threadIdx.x < st) s[threadIdx.x] += s[threadIdx.x + st];
        __syncthreads();
    }
    if (threadIdx.x < 32) atomicAdd(&g_colsum[threadIdx.x], s[threadIdx.x]);
}

// out = (colsum / N) @ Wfc + bfc; also resets g_deg (all consumers done).
__global__ void final_kernel(const float* __restrict__ Wfc,
                             const float* __restrict__ bfc,
                             float* __restrict__ out) {
    int t = blockIdx.x * blockDim.x + threadIdx.x;
    if (t < N_NODES) g_deg[t] = 0;           // safe: post2 already finished
    if (blockIdx.x == 0 && threadIdx.x < N_CLASSES) {
        int c = threadIdx.x;
        float acc = bfc[c];
        const float inv_n = 1.0f / (float)N_NODES;
#pragma unroll
        for (int f = 0; f < H2; f++)
            acc += (g_colsum[f] * inv_n) * Wfc[f * N_CLASSES + c];
        out[c] = acc;
    }
}

// ---------------- launch ------------------------------------------------------
extern "C" void kernel_launch(void* const* d_in, const int* in_sizes, int n_in,
                              void* d_out, int out_size) {
    const float* x   = (const float*)d_in[0];
    const float* W1  = (const float*)d_in[1];
    const float* b1  = (const float*)d_in[2];
    const float* W2  = (const float*)d_in[3];
    const float* b2  = (const float*)d_in[4];
    const float* Wfc = (const float*)d_in[5];
    const float* bfc = (const float*)d_in[6];
    const int*   ei  = (const int*)  d_in[7];
    float* out = (float*)d_out;

    hist_kernel<<<N_EDGES / 256, 256>>>(ei);

    gemm1_kernel<<<(N_NODES + 63) / 64, 256>>>(x, W1, b1);
    agg1_kernel<<<N_EDGES * 4 / 256, 256>>>(ei);

    gemm2_kernel<<<(N_NODES + 63) / 64, 128>>>(W2, b2);
    agg2_kernel<<<N_EDGES * 2 / 256, 256>>>(ei);

    post2_kernel<<<(N_NODES * H2 + 255) / 256, 256>>>();
    final_kernel<<<(N_NODES + 255) / 256, 256>>>(Wfc, bfc, out);
}

// round 12
// speedup vs baseline: 1.1669x; 1.1669x over previous
#include <cuda_runtime.h>
#include <cuda_fp16.h>
#include <cuda_bf16.h>

#define N_NODES   10000
#define N_EDGES   640000
#define F_IN      128
#define H1        64
#define H2        32
#define N_CLASSES 16

// ---------------- scratch (device globals) ----------------------------------
__device__ uint4 g_h1s [N_NODES * H1 / 8];   // h1 * dinv[n]  (fp16 payload)
__device__ uint4 g_agg1[N_NODES * H1 / 8];   // fp16 accum: init h1s + b1*rd
__device__ uint4 g_h2s [N_NODES * H2 / 8];   // h2 * dinv[n]  (fp16)
__device__ uint4 g_agg2[N_NODES * H2 / 8];   // fp16 accum: init h2s + b2*rd
__device__ int   g_deg [N_NODES];            // ALWAYS zero at launch entry
__device__ float g_colsum[H2];

// 16-byte vectorized fp16 reduction (no return), sm_90+
__device__ __forceinline__ void red_add_v4_f16x2(void* addr, uint4 a) {
    asm volatile("red.global.add.noftz.v4.f16x2 [%0], {%1,%2,%3,%4};"
                 :: "l"(addr), "r"(a.x), "r"(a.y), "r"(a.z), "r"(a.w)
                 : "memory");
}

// ---------------- degree histogram (+ colsum zero) ----------------------------
__global__ void hist_kernel(const int* __restrict__ ei) {
    int e = blockIdx.x * blockDim.x + threadIdx.x;
    if (blockIdx.x == 0 && threadIdx.x < H2) g_colsum[threadIdx.x] = 0.0f;
    if (e >= N_EDGES) return;
    atomicAdd(&g_deg[ei[N_EDGES + e]], 1);   // no-return -> RED
}

// ---------------- gemm1: h1 = x @ W1 -----------------------------------------
// 64 nodes x 64 outs, 256 threads, micro 4x4, two K chunks of 64.
// epilogue (fp16): h1s = h1*d;  agg1 = h1s + b1*rd  (true act = relu(agg1*d))
__global__ __launch_bounds__(256) void gemm1_kernel(const float* __restrict__ x,
                                                    const float* __restrict__ W1,
                                                    const float* __restrict__ b1) {
    __shared__ float Ws[64][64];
    __shared__ float Xt[64][68];

    const int tid = threadIdx.x;
    const int tx  = tid & 15;
    const int ty  = tid >> 4;
    const int node0 = blockIdx.x * 64;

    float acc[4][4];
#pragma unroll
    for (int i = 0; i < 4; i++)
#pragma unroll
        for (int j = 0; j < 4; j++) acc[i][j] = 0.0f;

    for (int kc = 0; kc < 2; kc++) {
        {
            int r  = tid >> 4;
            int c4 = (tid & 15) * 4;
#pragma unroll
            for (int p = 0; p < 4; p++) {
                int rr = r + p * 16;
                *(float4*)(&Ws[rr][c4]) =
                    *(const float4*)(W1 + (kc * 64 + rr) * H1 + c4);
            }
        }
        {
            int nl = tid & 63;
            int kq = (tid >> 6) * 4;
            int node = node0 + nl;
#pragma unroll
            for (int p = 0; p < 4; p++) {
                int k4 = kq + p * 16;
                float4 v = make_float4(0.f, 0.f, 0.f, 0.f);
                if (node < N_NODES)
                    v = *(const float4*)(x + node * F_IN + kc * 64 + k4);
                Xt[k4 + 0][nl] = v.x; Xt[k4 + 1][nl] = v.y;
                Xt[k4 + 2][nl] = v.z; Xt[k4 + 3][nl] = v.w;
            }
        }
        __syncthreads();

#pragma unroll 8
        for (int k = 0; k < 64; k++) {
            float4 wv = *(const float4*)(&Ws[k][tx * 4]);
            float4 xv = *(const float4*)(&Xt[k][ty * 4]);
            acc[0][0] += xv.x * wv.x; acc[0][1] += xv.x * wv.y;
            acc[0][2] += xv.x * wv.z; acc[0][3] += xv.x * wv.w;
            acc[1][0] += xv.y * wv.x; acc[1][1] += xv.y * wv.y;
            acc[1][2] += xv.y * wv.z; acc[1][3] += xv.y * wv.w;
            acc[2][0] += xv.z * wv.x; acc[2][1] += xv.z * wv.y;
            acc[2][2] += xv.z * wv.z; acc[2][3] += xv.z * wv.w;
            acc[3][0] += xv.w * wv.x; acc[3][1] += xv.w * wv.y;
            acc[3][2] += xv.w * wv.z; acc[3][3] += xv.w * wv.w;
        }
        __syncthreads();
    }

    float4 bv = *(const float4*)(b1 + tx * 4);
#pragma unroll
    for (int i = 0; i < 4; i++) {
        int node = node0 + ty * 4 + i;
        if (node < N_NODES) {
            float dp1 = (float)g_deg[node] + 1.0f;
            float d   = rsqrtf(dp1);
            float rd  = dp1 * d;              // sqrt(deg+1)
            float4 hs = make_float4(acc[i][0] * d, acc[i][1] * d,
                                    acc[i][2] * d, acc[i][3] * d);
            __half2 hp0 = __floats2half2_rn(hs.x, hs.y);
            __half2 hp1 = __floats2half2_rn(hs.z, hs.w);
            *(uint2*)((__half*)g_h1s + node * H1 + tx * 4) =
                make_uint2(*(unsigned*)&hp0, *(unsigned*)&hp1);
            __half2 ap0 = __floats2half2_rn(hs.x + bv.x * rd, hs.y + bv.y * rd);
            __half2 ap1 = __floats2half2_rn(hs.z + bv.z * rd, hs.w + bv.w * rd);
            *(uint2*)((__half*)g_agg1 + node * H1 + tx * 4) =
                make_uint2(*(unsigned*)&ap0, *(unsigned*)&ap1);
        }
    }
}

// ---------------- edge aggregation layer 1 -----------------------------------
// 8 threads per edge, 16B fp16 slice each: gather + one v4.f16x2 red. (R9 cfg)
__global__ void agg1_kernel(const int* __restrict__ ei) {
    long long t = (long long)blockIdx.x * blockDim.x + threadIdx.x;
    int e = (int)(t >> 3);
    int q = (int)(t & 7);
    if (e >= N_EDGES) return;
    int src = __ldg(&ei[e]);
    int dst = __ldg(&ei[N_EDGES + e]);
    uint4 a = g_h1s[src * 8 + q];                // 8 uint4 per 64-half row
    red_add_v4_f16x2(g_agg1 + dst * 8 + q, a);
}

// ---------------- gemm2: h2 = relu(agg1*d) @ W2 ------------------------------
// 64 nodes x 32 outs, 128 threads, micro 4x4; fp16 agg1 -> fp32 smem with
// deferred dinv + relu. epilogue (fp16): h2s = h2*d; agg2 = h2s + b2*rd.
__global__ __launch_bounds__(128) void gemm2_kernel(const float* __restrict__ W2,
                                                    const float* __restrict__ b2) {
    __shared__ float Ws[64][32];
    __shared__ float Xt[64][68];

    const int tid = threadIdx.x;
    const int tx  = tid & 7;
    const int ty  = tid >> 3;
    const int node0 = blockIdx.x * 64;

    {
        int r  = tid >> 3;
        int c4 = (tid & 7) * 4;
#pragma unroll
        for (int p = 0; p < 4; p++) {
            int rr = r + p * 16;
            *(float4*)(&Ws[rr][c4]) = *(const float4*)(W2 + rr * H2 + c4);
        }
    }
    {
        int nl = tid & 63;                 // node local
        int hsel = tid >> 6;               // 0/1 -> k half [0,32) or [32,64)
        int node = node0 + nl;
        float d = 0.f;
        if (node < N_NODES) d = rsqrtf((float)g_deg[node] + 1.0f);
#pragma unroll
        for (int p = 0; p < 4; p++) {
            int k8 = hsel * 32 + p * 8;
            uint4 raw = make_uint4(0, 0, 0, 0);
            if (node < N_NODES)
                raw = g_agg1[node * 8 + hsel * 4 + p];
            __half2* hp = (__half2*)&raw;
#pragma unroll
            for (int u = 0; u < 4; u++) {
                float2 f = __half22float2(hp[u]);
                Xt[k8 + u * 2 + 0][nl] = fmaxf(f.x * d, 0.f);
                Xt[k8 + u * 2 + 1][nl] = fmaxf(f.y * d, 0.f);
            }
        }
    }
    __syncthreads();

    float acc[4][4];
#pragma unroll
    for (int i = 0; i < 4; i++)
#pragma unroll
        for (int j = 0; j < 4; j++) acc[i][j] = 0.0f;

#pragma unroll 8
    for (int k = 0; k < 64; k++) {
        float4 wv = *(const float4*)(&Ws[k][tx * 4]);
        float4 xv = *(const float4*)(&Xt[k][ty * 4]);
        acc[0][0] += xv.x * wv.x; acc[0][1] += xv.x * wv.y;
        acc[0][2] += xv.x * wv.z; acc[0][3] += xv.x * wv.w;
        acc[1][0] += xv.y * wv.x; acc[1][1] += xv.y * wv.y;
        acc[1][2] += xv.y * wv.z; acc[1][3] += xv.y * wv.w;
        acc[2][0] += xv.z * wv.x; acc[2][1] += xv.z * wv.y;
        acc[2][2] += xv.z * wv.z; acc[2][3] += xv.z * wv.w;
        acc[3][0] += xv.w * wv.x; acc[3][1] += xv.w * wv.y;
        acc[3][2] += xv.w * wv.z; acc[3][3] += xv.w * wv.w;
    }

    float4 bv = *(const float4*)(b2 + tx * 4);
#pragma unroll
    for (int i = 0; i < 4; i++) {
        int node = node0 + ty * 4 + i;
        if (node < N_NODES) {
            float dp1 = (float)g_deg[node] + 1.0f;
            float d   = rsqrtf(dp1);
            float rd  = dp1 * d;
            float4 hs = make_float4(acc[i][0] * d, acc[i][1] * d,
                                    acc[i][2] * d, acc[i][3] * d);
            __half2 hp0 = __floats2half2_rn(hs.x, hs.y);
            __half2 hp1 = __floats2half2_rn(hs.z, hs.w);
            *(uint2*)((__half*)g_h2s + node * H2 + tx * 4) =
                make_uint2(*(unsigned*)&hp0, *(unsigned*)&hp1);
            __half2 ap0 = __floats2half2_rn(hs.x + bv.x * rd, hs.y + bv.y * rd);
            __half2 ap1 = __floats2half2_rn(hs.z + bv.z * rd, hs.w + bv.w * rd);
            *(uint2*)((__half*)g_agg2 + node * H2 + tx * 4) =
                make_uint2(*(unsigned*)&ap0, *(unsigned*)&ap1);
        }
    }
}

// ---------------- edge aggregation layer 2 -----------------------------------
// 4 threads per edge, 16B fp16 slice each: gather + one v4.f16x2 red. (R9 cfg)
__global__ void agg2_kernel(const int* __restrict__ ei) {
    long long t = (long long)blockIdx.x * blockDim.x + threadIdx.x;
    int e = (int)(t >> 2);
    int q = (int)(t & 3);
    if (e >= N_EDGES) return;
    int src = __ldg(&ei[e]);
    int dst = __ldg(&ei[N_EDGES + e]);
    uint4 a = g_h2s[src * 4 + q];                // 4 uint4 per 32-half row
    red_add_v4_f16x2(g_agg2 + dst * 4 + q, a);
}

// ---------------- layer-2 epilogue: relu(agg2*d) + mean-pool column sums -----
// Reads g_deg; reset is deferred to final_kernel (stream-ordered after).
__global__ void post2_kernel() {
    __shared__ float s[256];
    int t = blockIdx.x * blockDim.x + threadIdx.x;   // over N_NODES*H2
    float v = 0.0f;
    if (t < N_NODES * H2) {
        int n = t >> 5;
        float d = rsqrtf((float)g_deg[n] + 1.0f);
        float a = __half2float(((const __half*)g_agg2)[t]);
        v = fmaxf(a * d, 0.0f);
    }
    s[threadIdx.x] = v;
    __syncthreads();
#pragma unroll
    for (int st = 128; st >= 32; st >>= 1) {
        if (threadIdx.x < st) s[threadIdx.x] += s[threadIdx.x + st];
        __syncthreads();
    }
    if (threadIdx.x < 32) atomicAdd(&g_colsum[threadIdx.x], s[threadIdx.x]);
}

// out = (colsum / N) @ Wfc + bfc; also resets g_deg (all consumers done).
__global__ void final_kernel(const float* __restrict__ Wfc,
                             const float* __restrict__ bfc,
                             float* __restrict__ out) {
    int t = blockIdx.x * blockDim.x + threadIdx.x;
    if (t < N_NODES) g_deg[t] = 0;           // safe: post2 already finished
    if (blockIdx.x == 0 && threadIdx.x < N_CLASSES) {
        int c = threadIdx.x;
        float acc = bfc[c];
        const float inv_n = 1.0f / (float)N_NODES;
#pragma unroll
        for (int f = 0; f < H2; f++)
            acc += (g_colsum[f] * inv_n) * Wfc[f * N_CLASSES + c];
        out[c] = acc;
    }
}

// ---------------- launch ------------------------------------------------------
extern "C" void kernel_launch(void* const* d_in, const int* in_sizes, int n_in,
                              void* d_out, int out_size) {
    const float* x   = (const float*)d_in[0];
    const float* W1  = (const float*)d_in[1];
    const float* b1  = (const float*)d_in[2];
    const float* W2  = (const float*)d_in[3];
    const float* b2  = (const float*)d_in[4];
    const float* Wfc = (const float*)d_in[5];
    const float* bfc = (const float*)d_in[6];
    const int*   ei  = (const int*)  d_in[7];
    float* out = (float*)d_out;

    hist_kernel<<<N_EDGES / 256, 256>>>(ei);

    gemm1_kernel<<<(N_NODES + 63) / 64, 256>>>(x, W1, b1);
    agg1_kernel<<<N_EDGES * 8 / 256, 256>>>(ei);

    gemm2_kernel<<<(N_NODES + 63) / 64, 128>>>(W2, b2);
    agg2_kernel<<<N_EDGES * 4 / 256, 256>>>(ei);

    post2_kernel<<<(N_NODES * H2 + 255) / 256, 256>>>();
    final_kernel<<<(N_NODES + 255) / 256, 256>>>(Wfc, bfc, out);
}